// round 1
// baseline (speedup 1.0000x reference)
#include <cuda_runtime.h>
#include <math.h>

#define NTOK 2304
#define CIN  256
#define HID  512
#define QKV_M 1536

// Scratch (allocation-free rule: __device__ globals)
__device__ float g_qkv[2u * 1536u * 2304u];   // qkv output: [b][3*512][n]
__device__ float g_att[2u * 512u * 2304u];    // attention output: [b][512][n]

// ---------------------------------------------------------------------------
// Generic 128x128 tile SGEMM, K-step 8, 8x8 microtiles. C = A(MxK) * B(KxN) (+bias)
// A row-major [M][K], B row-major [K][N] (batched via strideB), C row-major.
// Requires M%128==0, N%128==0, K%8==0.
// ---------------------------------------------------------------------------
__global__ __launch_bounds__(256) void sgemm128(
    const float* __restrict__ A, const float* __restrict__ Bg,
    float* __restrict__ Cg, const float* __restrict__ bias,
    int M, int N, int K, long long strideB, long long strideC)
{
    __shared__ float As[8][128];
    __shared__ float Bs[8][128];

    const float* B = Bg + (long long)blockIdx.z * strideB;
    float*       C = Cg + (long long)blockIdx.z * strideC;

    const int m0 = blockIdx.y * 128;
    const int n0 = blockIdx.x * 128;
    const int tid = threadIdx.x;

    const int a_row = tid >> 1;            // 0..127
    const int a_col = (tid & 1) << 2;      // 0 or 4
    const int b_row = tid >> 5;            // 0..7
    const int b_col = (tid & 31) << 2;     // 0..124
    const int rm = (tid >> 4) << 3;        // 0..120
    const int rn = (tid & 15) << 3;        // 0..120

    float acc[8][8];
#pragma unroll
    for (int i = 0; i < 8; i++)
#pragma unroll
        for (int j = 0; j < 8; j++) acc[i][j] = 0.0f;

    for (int k0 = 0; k0 < K; k0 += 8) {
        float4 av = *(const float4*)(A + (long long)(m0 + a_row) * K + k0 + a_col);
        float4 bv = *(const float4*)(B + (long long)(k0 + b_row) * N + n0 + b_col);
        __syncthreads();   // previous iteration's compute done reading smem
        As[a_col + 0][a_row] = av.x;
        As[a_col + 1][a_row] = av.y;
        As[a_col + 2][a_row] = av.z;
        As[a_col + 3][a_row] = av.w;
        *(float4*)&Bs[b_row][b_col] = bv;
        __syncthreads();
#pragma unroll
        for (int kk = 0; kk < 8; kk++) {
            float a[8], bb[8];
            *(float4*)(a)      = *(float4*)&As[kk][rm];
            *(float4*)(a + 4)  = *(float4*)&As[kk][rm + 4];
            *(float4*)(bb)     = *(float4*)&Bs[kk][rn];
            *(float4*)(bb + 4) = *(float4*)&Bs[kk][rn + 4];
#pragma unroll
            for (int i = 0; i < 8; i++)
#pragma unroll
                for (int j = 0; j < 8; j++)
                    acc[i][j] = fmaf(a[i], bb[j], acc[i][j]);
        }
    }

#pragma unroll
    for (int i = 0; i < 8; i++) {
        float bsv = bias ? bias[m0 + rm + i] : 0.0f;
        float4 v0 = make_float4(acc[i][0] + bsv, acc[i][1] + bsv,
                                acc[i][2] + bsv, acc[i][3] + bsv);
        float4 v1 = make_float4(acc[i][4] + bsv, acc[i][5] + bsv,
                                acc[i][6] + bsv, acc[i][7] + bsv);
        float* cp = C + (long long)(m0 + rm + i) * N + n0 + rn;
        *(float4*)(cp)     = v0;
        *(float4*)(cp + 4) = v1;
    }
}

// ---------------------------------------------------------------------------
// L2-normalize q and k rows over the token dimension (in place).
// grid = (1024, B): blockIdx.x -> {qk in [0,2), row in [0,512)}
// ---------------------------------------------------------------------------
__global__ __launch_bounds__(256) void l2norm_qk(float* __restrict__ qkv)
{
    const int b = blockIdx.y;
    const int r = blockIdx.x;                       // 0..1023
    float* row = qkv + ((long long)b * 3 * HID + (r >> 9) * HID + (r & 511)) * NTOK;
    const int tid = threadIdx.x;

    float s = 0.0f;
    for (int i = tid; i < NTOK; i += 256) { float v = row[i]; s += v * v; }
#pragma unroll
    for (int o = 16; o >= 1; o >>= 1) s += __shfl_xor_sync(0xffffffffu, s, o);

    __shared__ float ws[8];
    if ((tid & 31) == 0) ws[tid >> 5] = s;
    __syncthreads();
    if (tid < 32) {
        float t = (tid < 8) ? ws[tid] : 0.0f;
#pragma unroll
        for (int o = 4; o >= 1; o >>= 1) t += __shfl_xor_sync(0xffffffffu, t, o);
        if (tid == 0) ws[0] = t;
    }
    __syncthreads();
    const float inv = 1.0f / fmaxf(sqrtf(ws[0]), 1e-12f);
    for (int i = tid; i < NTOK; i += 256) row[i] *= inv;
}

// ---------------------------------------------------------------------------
// Flash attention, one (b,h) head per blockIdx.y, 64-token n-tile per blockIdx.x.
// Q,K,V are [64 d][2304 n] row-major slices of g_qkv. Output [512][2304].
// 256 threads, 4x4 microtiles, online softmax, P reuses K's smem slot,
// V stored transposed + swizzled for conflict-free float4 reads.
// ---------------------------------------------------------------------------
__global__ __launch_bounds__(256) void flash_attn(
    const float* __restrict__ qkv, float* __restrict__ outp)
{
    __shared__ float sQ [64 * 64];
    __shared__ float sKP[64 * 64];   // K tile, then reused for P tile
    __shared__ float sVt[64 * 64];   // transposed V, swizzled columns

    const int b  = blockIdx.y >> 3;
    const int h  = blockIdx.y & 7;
    const int n0 = blockIdx.x * 64;

    const float* Q  = qkv + ((long long)b * 3 * HID + h * 64) * NTOK;
    const float* Kp = Q + (long long)HID * NTOK;
    const float* Vp = Q + (long long)2 * HID * NTOK;

    const int tid = threadIdx.x;
    const int lr = tid >> 4;   // 0..15  (n microtile row group)
    const int lc = tid & 15;   // 0..15  (m / d microtile col group)

    // Load Q tile: sQ[d][n]
#pragma unroll
    for (int it = 0; it < 4; it++) {
        int d = it * 16 + lr;
        *(float4*)&sQ[d * 64 + lc * 4] =
            *(const float4*)(Q + (long long)d * NTOK + n0 + lc * 4);
    }

    float o[4][4];
#pragma unroll
    for (int r = 0; r < 4; r++)
#pragma unroll
        for (int j = 0; j < 4; j++) o[r][j] = 0.0f;
    float rmax[4] = {-1e30f, -1e30f, -1e30f, -1e30f};
    float rsum[4] = {0.0f, 0.0f, 0.0f, 0.0f};

    for (int m0 = 0; m0 < NTOK; m0 += 64) {
        // Load K tile [d][m] and V tile transposed+swizzled: sVt[m][(d + (m&60)) & 63]
#pragma unroll
        for (int it = 0; it < 4; it++) {
            int d = it * 16 + lr;
            *(float4*)&sKP[d * 64 + lc * 4] =
                *(const float4*)(Kp + (long long)d * NTOK + m0 + lc * 4);
            float4 vv = *(const float4*)(Vp + (long long)d * NTOK + m0 + lc * 4);
            int c = (d + lc * 4) & 63;           // swizzle shift = m & 60 = 4*lc
            sVt[(lc * 4 + 0) * 64 + c] = vv.x;
            sVt[(lc * 4 + 1) * 64 + c] = vv.y;
            sVt[(lc * 4 + 2) * 64 + c] = vv.z;
            sVt[(lc * 4 + 3) * 64 + c] = vv.w;
        }
        __syncthreads();

        // S = Q^T K  (s[r][j]: n = n0+lr*4+r, m = m0+lc*4+j)
        float s[4][4];
#pragma unroll
        for (int r = 0; r < 4; r++)
#pragma unroll
            for (int j = 0; j < 4; j++) s[r][j] = 0.0f;
#pragma unroll
        for (int d = 0; d < 64; d++) {
            float4 qv = *(float4*)&sQ [d * 64 + lr * 4];
            float4 kv = *(float4*)&sKP[d * 64 + lc * 4];
            s[0][0] = fmaf(qv.x, kv.x, s[0][0]); s[0][1] = fmaf(qv.x, kv.y, s[0][1]);
            s[0][2] = fmaf(qv.x, kv.z, s[0][2]); s[0][3] = fmaf(qv.x, kv.w, s[0][3]);
            s[1][0] = fmaf(qv.y, kv.x, s[1][0]); s[1][1] = fmaf(qv.y, kv.y, s[1][1]);
            s[1][2] = fmaf(qv.y, kv.z, s[1][2]); s[1][3] = fmaf(qv.y, kv.w, s[1][3]);
            s[2][0] = fmaf(qv.z, kv.x, s[2][0]); s[2][1] = fmaf(qv.z, kv.y, s[2][1]);
            s[2][2] = fmaf(qv.z, kv.z, s[2][2]); s[2][3] = fmaf(qv.z, kv.w, s[2][3]);
            s[3][0] = fmaf(qv.w, kv.x, s[3][0]); s[3][1] = fmaf(qv.w, kv.y, s[3][1]);
            s[3][2] = fmaf(qv.w, kv.z, s[3][2]); s[3][3] = fmaf(qv.w, kv.w, s[3][3]);
        }

        // Online softmax per n-row (reduce across the 16-lane lc group)
#pragma unroll
        for (int r = 0; r < 4; r++) {
            float tm = fmaxf(fmaxf(s[r][0], s[r][1]), fmaxf(s[r][2], s[r][3]));
#pragma unroll
            for (int ofs = 8; ofs >= 1; ofs >>= 1)
                tm = fmaxf(tm, __shfl_xor_sync(0xffffffffu, tm, ofs, 16));
            float nm   = fmaxf(rmax[r], tm);
            float corr = __expf(rmax[r] - nm);
            rmax[r] = nm;
            float ps = 0.0f;
#pragma unroll
            for (int j = 0; j < 4; j++) { s[r][j] = __expf(s[r][j] - nm); ps += s[r][j]; }
#pragma unroll
            for (int ofs = 8; ofs >= 1; ofs >>= 1)
                ps += __shfl_xor_sync(0xffffffffu, ps, ofs, 16);
            rsum[r] = rsum[r] * corr + ps;
#pragma unroll
            for (int j = 0; j < 4; j++) o[r][j] *= corr;
        }
        __syncthreads();   // everyone done reading sKP as K

        // Write P into sKP: sKP[n][m]
#pragma unroll
        for (int r = 0; r < 4; r++)
            *(float4*)&sKP[(lr * 4 + r) * 64 + lc * 4] =
                make_float4(s[r][0], s[r][1], s[r][2], s[r][3]);
        __syncthreads();

        // O += P * V^T : o[r][j] over (n = lr*4+r, d = lc*4+j)
#pragma unroll
        for (int m = 0; m < 64; m++) {
            int c = (lc * 4 + (m & 60)) & 63;
            float4 vv = *(float4*)&sVt[m * 64 + c];
            float p0 = sKP[(lr * 4 + 0) * 64 + m];
            float p1 = sKP[(lr * 4 + 1) * 64 + m];
            float p2 = sKP[(lr * 4 + 2) * 64 + m];
            float p3 = sKP[(lr * 4 + 3) * 64 + m];
            o[0][0] = fmaf(p0, vv.x, o[0][0]); o[0][1] = fmaf(p0, vv.y, o[0][1]);
            o[0][2] = fmaf(p0, vv.z, o[0][2]); o[0][3] = fmaf(p0, vv.w, o[0][3]);
            o[1][0] = fmaf(p1, vv.x, o[1][0]); o[1][1] = fmaf(p1, vv.y, o[1][1]);
            o[1][2] = fmaf(p1, vv.z, o[1][2]); o[1][3] = fmaf(p1, vv.w, o[1][3]);
            o[2][0] = fmaf(p2, vv.x, o[2][0]); o[2][1] = fmaf(p2, vv.y, o[2][1]);
            o[2][2] = fmaf(p2, vv.z, o[2][2]); o[2][3] = fmaf(p2, vv.w, o[2][3]);
            o[3][0] = fmaf(p3, vv.x, o[3][0]); o[3][1] = fmaf(p3, vv.y, o[3][1]);
            o[3][2] = fmaf(p3, vv.z, o[3][2]); o[3][3] = fmaf(p3, vv.w, o[3][3]);
        }
        __syncthreads();   // before next tile overwrites sKP/sVt
    }

    // Epilogue: normalize by softmax denominator, write [d][n]
#pragma unroll
    for (int r = 0; r < 4; r++) {
        float inv = 1.0f / rsum[r];
        int n = n0 + lr * 4 + r;
#pragma unroll
        for (int j = 0; j < 4; j++) {
            int d = lc * 4 + j;
            outp[((long long)b * HID + h * 64 + d) * NTOK + n] = o[r][j] * inv;
        }
    }
}

// ---------------------------------------------------------------------------
extern "C" void kernel_launch(void* const* d_in, const int* in_sizes, int n_in,
                              void* d_out, int out_size)
{
    const float* x      = (const float*)d_in[0];   // (2, 256, 48, 48)
    const float* w_qkv  = (const float*)d_in[1];   // (1536, 256)
    const float* w_proj = (const float*)d_in[2];   // (256, 512)
    const float* b_proj = (const float*)d_in[3];   // (256,)
    float* y = (float*)d_out;                      // (2, 256, 48, 48)

    float *qkv_ptr = nullptr, *att_ptr = nullptr;
    cudaGetSymbolAddress((void**)&qkv_ptr, g_qkv);
    cudaGetSymbolAddress((void**)&att_ptr, g_att);

    // 1) qkv = w_qkv @ x  : per batch [1536,256] x [256,2304]
    sgemm128<<<dim3(NTOK / 128, QKV_M / 128, 2), 256>>>(
        w_qkv, x, qkv_ptr, nullptr,
        QKV_M, NTOK, CIN,
        (long long)CIN * NTOK, (long long)QKV_M * NTOK);

    // 2) L2-normalize q and k rows over the token dimension
    l2norm_qk<<<dim3(1024, 2), 256>>>(qkv_ptr);

    // 3) flash attention: 36 n-tiles x 16 (b,h) heads
    flash_attn<<<dim3(NTOK / 64, 16), 256>>>(qkv_ptr, att_ptr);

    // 4) y = w_proj @ att + bias : per batch [256,512] x [512,2304]
    sgemm128<<<dim3(NTOK / 128, CIN / 128, 2), 256>>>(
        w_proj, att_ptr, y, b_proj,
        CIN, NTOK, HID,
        (long long)HID * NTOK, (long long)CIN * NTOK);
}

// round 2
// speedup vs baseline: 1.9840x; 1.9840x over previous
#include <cuda_runtime.h>
#include <math.h>
#include <stdint.h>

#define NTOK 2304
#define CIN  256
#define HID  512
#define QKV_M 1536

// Scratch (allocation-free rule: __device__ globals)
__device__ float g_qkv[2u * 1536u * 2304u];   // qkv output: [b][3*512][n]
__device__ float g_att[2u * 512u * 2304u];    // attention output: [b][512][n]

// ---------------------------------------------------------------------------
// tf32 helpers + warp mma
// ---------------------------------------------------------------------------
__device__ __forceinline__ uint32_t f2tf32(float f) {
    uint32_t u;
    asm("cvt.rna.tf32.f32 %0, %1;" : "=r"(u) : "f"(f));
    return u;
}
__device__ __forceinline__ float f2tf32f(float f) { return __uint_as_float(f2tf32(f)); }

__device__ __forceinline__ void mma16n8k8(float* c, const uint32_t* a,
                                          uint32_t b0, uint32_t b1) {
    asm volatile(
        "mma.sync.aligned.m16n8k8.row.col.f32.tf32.tf32.f32 "
        "{%0,%1,%2,%3}, {%4,%5,%6,%7}, {%8,%9}, {%0,%1,%2,%3};\n"
        : "+f"(c[0]), "+f"(c[1]), "+f"(c[2]), "+f"(c[3])
        : "r"(a[0]), "r"(a[1]), "r"(a[2]), "r"(a[3]), "r"(b0), "r"(b1));
}

// ---------------------------------------------------------------------------
// 128x128 tile SGEMM (qkv). C = A(MxK) * B(KxN) (+bias), batched over z.
// ---------------------------------------------------------------------------
__global__ __launch_bounds__(256) void sgemm128(
    const float* __restrict__ A, const float* __restrict__ Bg,
    float* __restrict__ Cg, const float* __restrict__ bias,
    int M, int N, int K, long long strideB, long long strideC)
{
    __shared__ float As[8][128];
    __shared__ float Bs[8][128];

    const float* B = Bg + (long long)blockIdx.z * strideB;
    float*       C = Cg + (long long)blockIdx.z * strideC;

    const int m0 = blockIdx.y * 128;
    const int n0 = blockIdx.x * 128;
    const int tid = threadIdx.x;

    const int a_row = tid >> 1;
    const int a_col = (tid & 1) << 2;
    const int b_row = tid >> 5;
    const int b_col = (tid & 31) << 2;
    const int rm = (tid >> 4) << 3;
    const int rn = (tid & 15) << 3;

    float acc[8][8];
#pragma unroll
    for (int i = 0; i < 8; i++)
#pragma unroll
        for (int j = 0; j < 8; j++) acc[i][j] = 0.0f;

    for (int k0 = 0; k0 < K; k0 += 8) {
        float4 av = *(const float4*)(A + (long long)(m0 + a_row) * K + k0 + a_col);
        float4 bv = *(const float4*)(B + (long long)(k0 + b_row) * N + n0 + b_col);
        __syncthreads();
        As[a_col + 0][a_row] = av.x;
        As[a_col + 1][a_row] = av.y;
        As[a_col + 2][a_row] = av.z;
        As[a_col + 3][a_row] = av.w;
        *(float4*)&Bs[b_row][b_col] = bv;
        __syncthreads();
#pragma unroll
        for (int kk = 0; kk < 8; kk++) {
            float a[8], bb[8];
            *(float4*)(a)      = *(float4*)&As[kk][rm];
            *(float4*)(a + 4)  = *(float4*)&As[kk][rm + 4];
            *(float4*)(bb)     = *(float4*)&Bs[kk][rn];
            *(float4*)(bb + 4) = *(float4*)&Bs[kk][rn + 4];
#pragma unroll
            for (int i = 0; i < 8; i++)
#pragma unroll
                for (int j = 0; j < 8; j++)
                    acc[i][j] = fmaf(a[i], bb[j], acc[i][j]);
        }
    }

#pragma unroll
    for (int i = 0; i < 8; i++) {
        float bsv = bias ? bias[m0 + rm + i] : 0.0f;
        float4 v0 = make_float4(acc[i][0] + bsv, acc[i][1] + bsv,
                                acc[i][2] + bsv, acc[i][3] + bsv);
        float4 v1 = make_float4(acc[i][4] + bsv, acc[i][5] + bsv,
                                acc[i][6] + bsv, acc[i][7] + bsv);
        float* cp = C + (long long)(m0 + rm + i) * N + n0 + rn;
        *(float4*)(cp)     = v0;
        *(float4*)(cp + 4) = v1;
    }
}

// ---------------------------------------------------------------------------
// 64x128 tile SGEMM (proj: M=256 -> 4 M-tiles -> 144 blocks, 2x occupancy).
// ---------------------------------------------------------------------------
__global__ __launch_bounds__(128) void sgemm64(
    const float* __restrict__ A, const float* __restrict__ Bg,
    float* __restrict__ Cg, const float* __restrict__ bias,
    int M, int N, int K, long long strideB, long long strideC)
{
    __shared__ float As[8][64];
    __shared__ float Bs[8][128];

    const float* B = Bg + (long long)blockIdx.z * strideB;
    float*       C = Cg + (long long)blockIdx.z * strideC;

    const int m0 = blockIdx.y * 64;
    const int n0 = blockIdx.x * 128;
    const int tid = threadIdx.x;

    const int a_row = tid >> 1;            // 0..63
    const int a_col = (tid & 1) << 2;      // 0 or 4
    const int b_row = tid >> 5;            // 0..3 (plus +4 second pass)
    const int b_col = (tid & 31) << 2;
    const int rm = (tid >> 4) << 3;        // 0..56
    const int rn = (tid & 15) << 3;        // 0..120

    float acc[8][8];
#pragma unroll
    for (int i = 0; i < 8; i++)
#pragma unroll
        for (int j = 0; j < 8; j++) acc[i][j] = 0.0f;

    for (int k0 = 0; k0 < K; k0 += 8) {
        float4 av  = *(const float4*)(A + (long long)(m0 + a_row) * K + k0 + a_col);
        float4 bv0 = *(const float4*)(B + (long long)(k0 + b_row) * N + n0 + b_col);
        float4 bv1 = *(const float4*)(B + (long long)(k0 + b_row + 4) * N + n0 + b_col);
        __syncthreads();
        As[a_col + 0][a_row] = av.x;
        As[a_col + 1][a_row] = av.y;
        As[a_col + 2][a_row] = av.z;
        As[a_col + 3][a_row] = av.w;
        *(float4*)&Bs[b_row][b_col]     = bv0;
        *(float4*)&Bs[b_row + 4][b_col] = bv1;
        __syncthreads();
#pragma unroll
        for (int kk = 0; kk < 8; kk++) {
            float a[8], bb[8];
            *(float4*)(a)      = *(float4*)&As[kk][rm];
            *(float4*)(a + 4)  = *(float4*)&As[kk][rm + 4];
            *(float4*)(bb)     = *(float4*)&Bs[kk][rn];
            *(float4*)(bb + 4) = *(float4*)&Bs[kk][rn + 4];
#pragma unroll
            for (int i = 0; i < 8; i++)
#pragma unroll
                for (int j = 0; j < 8; j++)
                    acc[i][j] = fmaf(a[i], bb[j], acc[i][j]);
        }
    }

#pragma unroll
    for (int i = 0; i < 8; i++) {
        float bsv = bias ? bias[m0 + rm + i] : 0.0f;
        float4 v0 = make_float4(acc[i][0] + bsv, acc[i][1] + bsv,
                                acc[i][2] + bsv, acc[i][3] + bsv);
        float4 v1 = make_float4(acc[i][4] + bsv, acc[i][5] + bsv,
                                acc[i][6] + bsv, acc[i][7] + bsv);
        float* cp = C + (long long)(m0 + rm + i) * N + n0 + rn;
        *(float4*)(cp)     = v0;
        *(float4*)(cp + 4) = v1;
    }
}

// ---------------------------------------------------------------------------
// L2-normalize q and k rows over the token dimension (in place).
// ---------------------------------------------------------------------------
__global__ __launch_bounds__(256) void l2norm_qk(float* __restrict__ qkv)
{
    const int b = blockIdx.y;
    const int r = blockIdx.x;                       // 0..1023
    float* row = qkv + ((long long)b * 3 * HID + (r >> 9) * HID + (r & 511)) * NTOK;
    const int tid = threadIdx.x;

    float s = 0.0f;
    for (int i = tid; i < NTOK; i += 256) { float v = row[i]; s += v * v; }
#pragma unroll
    for (int o = 16; o >= 1; o >>= 1) s += __shfl_xor_sync(0xffffffffu, s, o);

    __shared__ float ws[8];
    if ((tid & 31) == 0) ws[tid >> 5] = s;
    __syncthreads();
    if (tid < 32) {
        float t = (tid < 8) ? ws[tid] : 0.0f;
#pragma unroll
        for (int o = 4; o >= 1; o >>= 1) t += __shfl_xor_sync(0xffffffffu, t, o);
        if (tid == 0) ws[0] = t;
    }
    __syncthreads();
    const float inv = 1.0f / fmaxf(sqrtf(ws[0]), 1e-12f);
    for (int i = tid; i < NTOK; i += 256) row[i] *= inv;
}

// ---------------------------------------------------------------------------
// Tensor-core flash attention (tf32 warp mma).
// Block = 128 threads (4 warps), one (b,h) head (blockIdx.y), 64-token n-tile
// (blockIdx.x). Per KV tile of 64 keys:
//   phase A: warp w computes S rows n in [w*16,(w+1)*16) x 64 m via mma
//            (Q^T fragments cached in registers for the whole loop),
//            online softmax in C-fragments, writes P (exp, max-shifted) + corr
//            factors to smem.
//   phase B: warp w computes O^T strip d in [w*16,(w+1)*16) x 64 n:
//            O^T += V * P^T  (A=V straight from smem, no transpose needed).
// Smem strides chosen for conflict-free mma fragment loads:
//   sK stride 72: bank(8*tg+g) distinct; sV/sP stride 68: bank(4*g+tg) distinct.
// ---------------------------------------------------------------------------
#define SK_STRIDE 72
#define SV_STRIDE 68
#define SP_STRIDE 68
#define FLASH_SMEM ((64 * SK_STRIDE + 64 * SV_STRIDE + 64 * SP_STRIDE + 64) * 4)

__global__ __launch_bounds__(128) void flash_attn_tc(
    const float* __restrict__ qkv, float* __restrict__ outp)
{
    extern __shared__ float sm[];
    float* sK = sm;                        // 64 x 72  (K tile, [d][m], tf32)
    float* sV = sK + 64 * SK_STRIDE;       // 64 x 68  (V tile, [d][m], tf32)
    float* sP = sV + 64 * SV_STRIDE;       // 64 x 68  (P tile, [n][m], tf32)
    float* sC = sP + 64 * SP_STRIDE;       // 64       (corr factors / final sums)

    const int b  = blockIdx.y >> 3;
    const int h  = blockIdx.y & 7;
    const int n0 = blockIdx.x * 64;

    const float* Q  = qkv + ((long long)(b * 3 * HID + h * 64)) * NTOK;
    const float* Kp = Q + (long long)HID * NTOK;
    const float* Vp = Q + 2LL * HID * NTOK;

    const int tid  = threadIdx.x;
    const int w    = tid >> 5;
    const int lane = tid & 31;
    const int g    = lane >> 2;   // group row (0..7)
    const int tg   = lane & 3;    // thread in group (0..3)

    // Q^T A-fragments in registers: rows n = n0 + w*16 + g (+8),
    // cols d = k*8 + tg (+4). Loaded once, reused for all 36 KV tiles.
    uint32_t qa[8][4];
    {
        const int nA = n0 + w * 16 + g;
#pragma unroll
        for (int k = 0; k < 8; k++) {
            const int d0 = k * 8 + tg;
            qa[k][0] = f2tf32(Q[(long long)d0 * NTOK + nA]);
            qa[k][1] = f2tf32(Q[(long long)d0 * NTOK + nA + 8]);
            qa[k][2] = f2tf32(Q[(long long)(d0 + 4) * NTOK + nA]);
            qa[k][3] = f2tf32(Q[(long long)(d0 + 4) * NTOK + nA + 8]);
        }
    }

    // O^T accumulators: warp strip d in [w*16,(w+1)*16), 8 n-tiles of 8.
    float oc[8][4];
#pragma unroll
    for (int t = 0; t < 8; t++)
#pragma unroll
        for (int j = 0; j < 4; j++) oc[t][j] = 0.0f;

    float rmax[2] = {-1e30f, -1e30f};
    float rsum[2] = {0.0f, 0.0f};

    for (int m0 = 0; m0 < NTOK; m0 += 64) {
        __syncthreads();   // prev phase B done with sV/sP/sC, prev A with sK

        // Load K and V tiles (tf32-rounded)
#pragma unroll
        for (int p = 0; p < 8; p++) {
            const int idx = p * 512 + tid * 4;
            const int d = idx >> 6, m = idx & 63;
            float4 kv = *(const float4*)(Kp + (long long)d * NTOK + m0 + m);
            float4 vv = *(const float4*)(Vp + (long long)d * NTOK + m0 + m);
            float* kd = sK + d * SK_STRIDE + m;
            kd[0] = f2tf32f(kv.x); kd[1] = f2tf32f(kv.y);
            kd[2] = f2tf32f(kv.z); kd[3] = f2tf32f(kv.w);
            float* vd = sV + d * SV_STRIDE + m;
            vd[0] = f2tf32f(vv.x); vd[1] = f2tf32f(vv.y);
            vd[2] = f2tf32f(vv.z); vd[3] = f2tf32f(vv.w);
        }
        __syncthreads();

        // ---- Phase A: S = Q^T K (16 rows x 64 cols per warp) ----
        float sc[8][4];
#pragma unroll
        for (int t = 0; t < 8; t++)
#pragma unroll
            for (int j = 0; j < 4; j++) sc[t][j] = 0.0f;

#pragma unroll
        for (int k = 0; k < 8; k++) {
            const float* kb0 = sK + (k * 8 + tg) * SK_STRIDE + g;
            const float* kb1 = sK + (k * 8 + tg + 4) * SK_STRIDE + g;
#pragma unroll
            for (int t = 0; t < 8; t++) {
                uint32_t b0 = __float_as_uint(kb0[t * 8]);
                uint32_t b1 = __float_as_uint(kb1[t * 8]);
                mma16n8k8(sc[t], qa[k], b0, b1);
            }
        }

        // ---- Online softmax on C-fragments ----
        const int nloc = w * 16 + g;   // row for r=0; r=1 adds 8
#pragma unroll
        for (int r = 0; r < 2; r++) {
            float mx = -1e30f;
#pragma unroll
            for (int t = 0; t < 8; t++)
                mx = fmaxf(mx, fmaxf(sc[t][2 * r], sc[t][2 * r + 1]));
            mx = fmaxf(mx, __shfl_xor_sync(0xffffffffu, mx, 1));
            mx = fmaxf(mx, __shfl_xor_sync(0xffffffffu, mx, 2));
            const float nm   = fmaxf(rmax[r], mx);
            const float corr = __expf(rmax[r] - nm);
            rmax[r] = nm;
            float ps = 0.0f;
            float* prow = sP + (nloc + 8 * r) * SP_STRIDE + 2 * tg;
#pragma unroll
            for (int t = 0; t < 8; t++) {
                float e0 = __expf(sc[t][2 * r] - nm);
                float e1 = __expf(sc[t][2 * r + 1] - nm);
                ps += e0 + e1;
                prow[t * 8]     = f2tf32f(e0);
                prow[t * 8 + 1] = f2tf32f(e1);
            }
            ps += __shfl_xor_sync(0xffffffffu, ps, 1);
            ps += __shfl_xor_sync(0xffffffffu, ps, 2);
            rsum[r] = rsum[r] * corr + ps;
            if (tg == 0) sC[nloc + 8 * r] = corr;
        }
        __syncthreads();

        // ---- Phase B: O^T += V * P^T ----
        // Rescale O by this tile's correction factors (per column n).
#pragma unroll
        for (int t = 0; t < 8; t++) {
            float c0 = sC[t * 8 + 2 * tg];
            float c1 = sC[t * 8 + 2 * tg + 1];
            oc[t][0] *= c0; oc[t][1] *= c1;
            oc[t][2] *= c0; oc[t][3] *= c1;
        }
#pragma unroll
        for (int k = 0; k < 8; k++) {
            const float* va = sV + (w * 16 + g) * SV_STRIDE + k * 8 + tg;
            uint32_t a[4];
            a[0] = __float_as_uint(va[0]);
            a[1] = __float_as_uint(va[8 * SV_STRIDE]);
            a[2] = __float_as_uint(va[4]);
            a[3] = __float_as_uint(va[8 * SV_STRIDE + 4]);
            const float* pb = sP + g * SP_STRIDE + k * 8 + tg;
#pragma unroll
            for (int t = 0; t < 8; t++) {
                uint32_t b0 = __float_as_uint(pb[t * 8 * SP_STRIDE]);
                uint32_t b1 = __float_as_uint(pb[t * 8 * SP_STRIDE + 4]);
                mma16n8k8(oc[t], a, b0, b1);
            }
        }
    }

    // ---- Epilogue: share row sums, normalize, write O^T[d][n] ----
    __syncthreads();
    if (tg == 0) {
        sC[w * 16 + g]     = rsum[0];
        sC[w * 16 + g + 8] = rsum[1];
    }
    __syncthreads();

    float* Op = outp + ((long long)(b * HID + h * 64 + w * 16)) * NTOK + n0;
#pragma unroll
    for (int t = 0; t < 8; t++) {
        const int n = t * 8 + 2 * tg;
        const float i0 = 1.0f / sC[n];
        const float i1 = 1.0f / sC[n + 1];
        Op[(long long)g * NTOK + n]           = oc[t][0] * i0;
        Op[(long long)g * NTOK + n + 1]       = oc[t][1] * i1;
        Op[(long long)(g + 8) * NTOK + n]     = oc[t][2] * i0;
        Op[(long long)(g + 8) * NTOK + n + 1] = oc[t][3] * i1;
    }
}

// ---------------------------------------------------------------------------
extern "C" void kernel_launch(void* const* d_in, const int* in_sizes, int n_in,
                              void* d_out, int out_size)
{
    const float* x      = (const float*)d_in[0];   // (2, 256, 48, 48)
    const float* w_qkv  = (const float*)d_in[1];   // (1536, 256)
    const float* w_proj = (const float*)d_in[2];   // (256, 512)
    const float* b_proj = (const float*)d_in[3];   // (256,)
    float* y = (float*)d_out;                      // (2, 256, 48, 48)

    float *qkv_ptr = nullptr, *att_ptr = nullptr;
    cudaGetSymbolAddress((void**)&qkv_ptr, g_qkv);
    cudaGetSymbolAddress((void**)&att_ptr, g_att);

    cudaFuncSetAttribute(flash_attn_tc,
                         cudaFuncAttributeMaxDynamicSharedMemorySize, FLASH_SMEM);

    // 1) qkv = w_qkv @ x  : per batch [1536,256] x [256,2304]
    sgemm128<<<dim3(NTOK / 128, QKV_M / 128, 2), 256>>>(
        w_qkv, x, qkv_ptr, nullptr,
        QKV_M, NTOK, CIN,
        (long long)CIN * NTOK, (long long)QKV_M * NTOK);

    // 2) L2-normalize q and k rows over the token dimension
    l2norm_qk<<<dim3(1024, 2), 256>>>(qkv_ptr);

    // 3) tensor-core flash attention: 36 n-tiles x 16 (b,h) heads
    flash_attn_tc<<<dim3(NTOK / 64, 16), 128, FLASH_SMEM>>>(qkv_ptr, att_ptr);

    // 4) y = w_proj @ att + bias : per batch [256,512] x [512,2304]
    sgemm64<<<dim3(NTOK / 128, CIN / 64, 2), 128>>>(
        w_proj, att_ptr, y, b_proj,
        CIN, NTOK, HID,
        (long long)HID * NTOK, (long long)CIN * NTOK);
}

// round 4
// speedup vs baseline: 2.6631x; 1.3423x over previous
#include <cuda_runtime.h>
#include <math.h>
#include <stdint.h>

#define NTOK 2304
#define CIN  256
#define HID  512
#define QKV_M 1536

// Scratch (allocation-free rule: __device__ globals)
__device__ float g_qkv[2u * 1536u * 2304u];   // qkv output: [b][3*512][n]
__device__ float g_att[2u * 512u * 2304u];    // attention output: [b][512][n]

// ---------------------------------------------------------------------------
// tf32 helpers + warp mma
// ---------------------------------------------------------------------------
__device__ __forceinline__ uint32_t f2tf32(float f) {
    uint32_t u;
    asm("cvt.rna.tf32.f32 %0, %1;" : "=r"(u) : "f"(f));
    return u;
}
__device__ __forceinline__ float f2tf32f(float f) { return __uint_as_float(f2tf32(f)); }

__device__ __forceinline__ void mma16n8k8(float* c, const uint32_t* a,
                                          uint32_t b0, uint32_t b1) {
    asm volatile(
        "mma.sync.aligned.m16n8k8.row.col.f32.tf32.tf32.f32 "
        "{%0,%1,%2,%3}, {%4,%5,%6,%7}, {%8,%9}, {%0,%1,%2,%3};\n"
        : "+f"(c[0]), "+f"(c[1]), "+f"(c[2]), "+f"(c[3])
        : "r"(a[0]), "r"(a[1]), "r"(a[2]), "r"(a[3]), "r"(b0), "r"(b1));
}

// ---------------------------------------------------------------------------
// tf32 tensor-core GEMM: C = A(MxK) * B(KxN) (+bias), batched over blockIdx.z.
// A row-major [M][K], B row-major [K][N]. BM x BN block tile, BK=16.
// Warp grid WMN x WNN; each warp computes 32 x 64 (2 m-tiles x 8 n-tiles of
// m16n8k8). Smem strides = BM+8 / BN+8 (≡ 8 mod 32) -> conflict-free fragment
// loads: bank = 8*tg + g + const covers all 32 banks.
// Requires M%BM==0, N%BN==0, K%16==0.
// ---------------------------------------------------------------------------
template<int BM, int BN, int WMN, int WNN>
__global__ __launch_bounds__(WMN * WNN * 32) void tf32gemm(
    const float* __restrict__ A, const float* __restrict__ Bg,
    float* __restrict__ Cg, const float* __restrict__ bias,
    int M, int N, int K, long long strideB, long long strideC)
{
    constexpr int THREADS = WMN * WNN * 32;
    constexpr int ASTR = BM + 8;
    constexpr int BSTR = BN + 8;
    constexpr int WM = BM / WMN;            // 32
    constexpr int WN = BN / WNN;            // 64
    constexpr int MT = WM / 16;             // 2
    constexpr int NT = WN / 8;              // 8
    constexpr int A_F4_PER_T = BM * 4 / THREADS;
    constexpr int B_F4_PER_T = BN * 4 / THREADS;

    __shared__ float As[16 * ASTR];
    __shared__ float Bs[16 * BSTR];

    const float* B = Bg + (long long)blockIdx.z * strideB;
    float*       C = Cg + (long long)blockIdx.z * strideC;

    const int m0 = blockIdx.y * BM;
    const int n0 = blockIdx.x * BN;
    const int tid  = threadIdx.x;
    const int w    = tid >> 5;
    const int lane = tid & 31;
    const int g    = lane >> 2;
    const int tg   = lane & 3;
    const int wm   = (w % WMN) * WM;
    const int wn   = (w / WMN) * WN;

    float acc[MT][NT][4];
#pragma unroll
    for (int mt = 0; mt < MT; mt++)
#pragma unroll
        for (int nt = 0; nt < NT; nt++)
#pragma unroll
            for (int j = 0; j < 4; j++) acc[mt][nt][j] = 0.0f;

    for (int k0 = 0; k0 < K; k0 += 16) {
        // Load A tile (BM x 16) -> As[k][m] (transposed), tf32-rounded.
        float4 av[A_F4_PER_T];
        int ar[A_F4_PER_T], ac[A_F4_PER_T];
#pragma unroll
        for (int i = 0; i < A_F4_PER_T; i++) {
            int idx = i * THREADS + tid;
            ar[i] = idx >> 2;               // 0..BM-1
            ac[i] = (idx & 3) << 2;         // 0,4,8,12
            av[i] = *(const float4*)(A + (long long)(m0 + ar[i]) * K + k0 + ac[i]);
        }
        // Load B tile (16 x BN) -> Bs[k][n]
        float4 bv[B_F4_PER_T];
        int br[B_F4_PER_T], bc[B_F4_PER_T];
#pragma unroll
        for (int i = 0; i < B_F4_PER_T; i++) {
            int idx = i * THREADS + tid;
            br[i] = idx / (BN / 4);
            bc[i] = (idx % (BN / 4)) << 2;
            bv[i] = *(const float4*)(B + (long long)(k0 + br[i]) * N + n0 + bc[i]);
        }
        __syncthreads();
#pragma unroll
        for (int i = 0; i < A_F4_PER_T; i++) {
            As[(ac[i] + 0) * ASTR + ar[i]] = f2tf32f(av[i].x);
            As[(ac[i] + 1) * ASTR + ar[i]] = f2tf32f(av[i].y);
            As[(ac[i] + 2) * ASTR + ar[i]] = f2tf32f(av[i].z);
            As[(ac[i] + 3) * ASTR + ar[i]] = f2tf32f(av[i].w);
        }
#pragma unroll
        for (int i = 0; i < B_F4_PER_T; i++) {
            float* bd = Bs + br[i] * BSTR + bc[i];
            bd[0] = f2tf32f(bv[i].x); bd[1] = f2tf32f(bv[i].y);
            bd[2] = f2tf32f(bv[i].z); bd[3] = f2tf32f(bv[i].w);
        }
        __syncthreads();

#pragma unroll
        for (int ks = 0; ks < 16; ks += 8) {
            uint32_t afr[MT][4];
#pragma unroll
            for (int mt = 0; mt < MT; mt++) {
                const int rb = wm + mt * 16;
                afr[mt][0] = __float_as_uint(As[(ks + tg)     * ASTR + rb + g]);
                afr[mt][1] = __float_as_uint(As[(ks + tg)     * ASTR + rb + g + 8]);
                afr[mt][2] = __float_as_uint(As[(ks + tg + 4) * ASTR + rb + g]);
                afr[mt][3] = __float_as_uint(As[(ks + tg + 4) * ASTR + rb + g + 8]);
            }
#pragma unroll
            for (int nt = 0; nt < NT; nt++) {
                uint32_t b0 = __float_as_uint(Bs[(ks + tg)     * BSTR + wn + nt * 8 + g]);
                uint32_t b1 = __float_as_uint(Bs[(ks + tg + 4) * BSTR + wn + nt * 8 + g]);
#pragma unroll
                for (int mt = 0; mt < MT; mt++)
                    mma16n8k8(acc[mt][nt], afr[mt], b0, b1);
            }
        }
        __syncthreads();
    }

    // Epilogue: write C (+bias), float2 per fragment half-row.
#pragma unroll
    for (int mt = 0; mt < MT; mt++) {
        const int r0 = m0 + wm + mt * 16 + g;
        const float bs0 = bias ? bias[r0]     : 0.0f;
        const float bs1 = bias ? bias[r0 + 8] : 0.0f;
#pragma unroll
        for (int nt = 0; nt < NT; nt++) {
            const int cidx = n0 + wn + nt * 8 + 2 * tg;
            *(float2*)(C + (long long)r0 * N + cidx) =
                make_float2(acc[mt][nt][0] + bs0, acc[mt][nt][1] + bs0);
            *(float2*)(C + (long long)(r0 + 8) * N + cidx) =
                make_float2(acc[mt][nt][2] + bs1, acc[mt][nt][3] + bs1);
        }
    }
}

// ---------------------------------------------------------------------------
// L2-normalize q and k rows over the token dimension (in place).
// ---------------------------------------------------------------------------
__global__ __launch_bounds__(256) void l2norm_qk(float* __restrict__ qkv)
{
    const int b = blockIdx.y;
    const int r = blockIdx.x;                       // 0..1023
    float* row = qkv + ((long long)b * 3 * HID + (r >> 9) * HID + (r & 511)) * NTOK;
    const int tid = threadIdx.x;

    float s = 0.0f;
    for (int i = tid; i < NTOK; i += 256) { float v = row[i]; s += v * v; }
#pragma unroll
    for (int o = 16; o >= 1; o >>= 1) s += __shfl_xor_sync(0xffffffffu, s, o);

    __shared__ float ws[8];
    if ((tid & 31) == 0) ws[tid >> 5] = s;
    __syncthreads();
    if (tid < 32) {
        float t = (tid < 8) ? ws[tid] : 0.0f;
#pragma unroll
        for (int o = 4; o >= 1; o >>= 1) t += __shfl_xor_sync(0xffffffffu, t, o);
        if (tid == 0) ws[0] = t;
    }
    __syncthreads();
    const float inv = 1.0f / fmaxf(sqrtf(ws[0]), 1e-12f);
    for (int i = tid; i < NTOK; i += 256) row[i] *= inv;
}

// ---------------------------------------------------------------------------
// Tensor-core flash attention (tf32 warp mma). See R2 notes.
// ---------------------------------------------------------------------------
#define SK_STRIDE 72
#define SV_STRIDE 68
#define SP_STRIDE 68
#define FLASH_SMEM ((64 * SK_STRIDE + 64 * SV_STRIDE + 64 * SP_STRIDE + 64) * 4)

__global__ __launch_bounds__(128) void flash_attn_tc(
    const float* __restrict__ qkv, float* __restrict__ outp)
{
    extern __shared__ float sm[];
    float* sK = sm;                        // 64 x 72  (K tile, [d][m], tf32)
    float* sV = sK + 64 * SK_STRIDE;       // 64 x 68  (V tile, [d][m], tf32)
    float* sP = sV + 64 * SV_STRIDE;       // 64 x 68  (P tile, [n][m], tf32)
    float* sC = sP + 64 * SP_STRIDE;       // 64       (corr factors / final sums)

    const int b  = blockIdx.y >> 3;
    const int h  = blockIdx.y & 7;
    const int n0 = blockIdx.x * 64;

    const float* Q  = qkv + ((long long)(b * 3 * HID + h * 64)) * NTOK;
    const float* Kp = Q + (long long)HID * NTOK;
    const float* Vp = Q + 2LL * HID * NTOK;

    const int tid  = threadIdx.x;
    const int w    = tid >> 5;
    const int lane = tid & 31;
    const int g    = lane >> 2;   // group row (0..7)
    const int tg   = lane & 3;    // thread in group (0..3)

    // Q^T A-fragments in registers, reused for all 36 KV tiles.
    uint32_t qa[8][4];
    {
        const int nA = n0 + w * 16 + g;
#pragma unroll
        for (int k = 0; k < 8; k++) {
            const int d0 = k * 8 + tg;
            qa[k][0] = f2tf32(Q[(long long)d0 * NTOK + nA]);
            qa[k][1] = f2tf32(Q[(long long)d0 * NTOK + nA + 8]);
            qa[k][2] = f2tf32(Q[(long long)(d0 + 4) * NTOK + nA]);
            qa[k][3] = f2tf32(Q[(long long)(d0 + 4) * NTOK + nA + 8]);
        }
    }

    float oc[8][4];
#pragma unroll
    for (int t = 0; t < 8; t++)
#pragma unroll
        for (int j = 0; j < 4; j++) oc[t][j] = 0.0f;

    float rmax[2] = {-1e30f, -1e30f};
    float rsum[2] = {0.0f, 0.0f};

    for (int m0 = 0; m0 < NTOK; m0 += 64) {
        __syncthreads();

        // Load K and V tiles (tf32-rounded)
#pragma unroll
        for (int p = 0; p < 8; p++) {
            const int idx = p * 512 + tid * 4;
            const int d = idx >> 6, m = idx & 63;
            float4 kv = *(const float4*)(Kp + (long long)d * NTOK + m0 + m);
            float4 vv = *(const float4*)(Vp + (long long)d * NTOK + m0 + m);
            float* kd = sK + d * SK_STRIDE + m;
            kd[0] = f2tf32f(kv.x); kd[1] = f2tf32f(kv.y);
            kd[2] = f2tf32f(kv.z); kd[3] = f2tf32f(kv.w);
            float* vd = sV + d * SV_STRIDE + m;
            vd[0] = f2tf32f(vv.x); vd[1] = f2tf32f(vv.y);
            vd[2] = f2tf32f(vv.z); vd[3] = f2tf32f(vv.w);
        }
        __syncthreads();

        // ---- Phase A: S = Q^T K ----
        float sc[8][4];
#pragma unroll
        for (int t = 0; t < 8; t++)
#pragma unroll
            for (int j = 0; j < 4; j++) sc[t][j] = 0.0f;

#pragma unroll
        for (int k = 0; k < 8; k++) {
            const float* kb0 = sK + (k * 8 + tg) * SK_STRIDE + g;
            const float* kb1 = sK + (k * 8 + tg + 4) * SK_STRIDE + g;
#pragma unroll
            for (int t = 0; t < 8; t++) {
                uint32_t b0 = __float_as_uint(kb0[t * 8]);
                uint32_t b1 = __float_as_uint(kb1[t * 8]);
                mma16n8k8(sc[t], qa[k], b0, b1);
            }
        }

        // ---- Online softmax ----
        const int nloc = w * 16 + g;
#pragma unroll
        for (int r = 0; r < 2; r++) {
            float mx = -1e30f;
#pragma unroll
            for (int t = 0; t < 8; t++)
                mx = fmaxf(mx, fmaxf(sc[t][2 * r], sc[t][2 * r + 1]));
            mx = fmaxf(mx, __shfl_xor_sync(0xffffffffu, mx, 1));
            mx = fmaxf(mx, __shfl_xor_sync(0xffffffffu, mx, 2));
            const float nm   = fmaxf(rmax[r], mx);
            const float corr = __expf(rmax[r] - nm);
            rmax[r] = nm;
            float ps = 0.0f;
            float* prow = sP + (nloc + 8 * r) * SP_STRIDE + 2 * tg;
#pragma unroll
            for (int t = 0; t < 8; t++) {
                float e0 = __expf(sc[t][2 * r] - nm);
                float e1 = __expf(sc[t][2 * r + 1] - nm);
                ps += e0 + e1;
                prow[t * 8]     = f2tf32f(e0);
                prow[t * 8 + 1] = f2tf32f(e1);
            }
            ps += __shfl_xor_sync(0xffffffffu, ps, 1);
            ps += __shfl_xor_sync(0xffffffffu, ps, 2);
            rsum[r] = rsum[r] * corr + ps;
            if (tg == 0) sC[nloc + 8 * r] = corr;
        }
        __syncthreads();

        // ---- Phase B: O^T += V * P^T ----
#pragma unroll
        for (int t = 0; t < 8; t++) {
            float c0 = sC[t * 8 + 2 * tg];
            float c1 = sC[t * 8 + 2 * tg + 1];
            oc[t][0] *= c0; oc[t][1] *= c1;
            oc[t][2] *= c0; oc[t][3] *= c1;
        }
#pragma unroll
        for (int k = 0; k < 8; k++) {
            const float* va = sV + (w * 16 + g) * SV_STRIDE + k * 8 + tg;
            uint32_t a[4];
            a[0] = __float_as_uint(va[0]);
            a[1] = __float_as_uint(va[8 * SV_STRIDE]);
            a[2] = __float_as_uint(va[4]);
            a[3] = __float_as_uint(va[8 * SV_STRIDE + 4]);
            const float* pb = sP + g * SP_STRIDE + k * 8 + tg;
#pragma unroll
            for (int t = 0; t < 8; t++) {
                uint32_t b0 = __float_as_uint(pb[t * 8 * SP_STRIDE]);
                uint32_t b1 = __float_as_uint(pb[t * 8 * SP_STRIDE + 4]);
                mma16n8k8(oc[t], a, b0, b1);
            }
        }
    }

    // ---- Epilogue ----
    __syncthreads();
    if (tg == 0) {
        sC[w * 16 + g]     = rsum[0];
        sC[w * 16 + g + 8] = rsum[1];
    }
    __syncthreads();

    float* Op = outp + ((long long)(b * HID + h * 64 + w * 16)) * NTOK + n0;
#pragma unroll
    for (int t = 0; t < 8; t++) {
        const int n = t * 8 + 2 * tg;
        const float i0 = 1.0f / sC[n];
        const float i1 = 1.0f / sC[n + 1];
        Op[(long long)g * NTOK + n]           = oc[t][0] * i0;
        Op[(long long)g * NTOK + n + 1]       = oc[t][1] * i1;
        Op[(long long)(g + 8) * NTOK + n]     = oc[t][2] * i0;
        Op[(long long)(g + 8) * NTOK + n + 1] = oc[t][3] * i1;
    }
}

// ---------------------------------------------------------------------------
extern "C" void kernel_launch(void* const* d_in, const int* in_sizes, int n_in,
                              void* d_out, int out_size)
{
    const float* x      = (const float*)d_in[0];   // (2, 256, 48, 48)
    const float* w_qkv  = (const float*)d_in[1];   // (1536, 256)
    const float* w_proj = (const float*)d_in[2];   // (256, 512)
    const float* b_proj = (const float*)d_in[3];   // (256,)
    float* y = (float*)d_out;                      // (2, 256, 48, 48)

    float *qkv_ptr = nullptr, *att_ptr = nullptr;
    cudaGetSymbolAddress((void**)&qkv_ptr, g_qkv);
    cudaGetSymbolAddress((void**)&att_ptr, g_att);

    cudaFuncSetAttribute(flash_attn_tc,
                         cudaFuncAttributeMaxDynamicSharedMemorySize, FLASH_SMEM);

    // 1) qkv = w_qkv @ x : per batch [1536,256] x [256,2304]; 128x128 tiles,
    //    8 warps -> grid 18*12*2 = 432 blocks
    tf32gemm<128, 128, 4, 2><<<dim3(NTOK / 128, QKV_M / 128, 2), 256>>>(
        w_qkv, x, qkv_ptr, nullptr,
        QKV_M, NTOK, CIN,
        (long long)CIN * NTOK, (long long)QKV_M * NTOK);

    // 2) L2-normalize q and k rows over the token dimension
    l2norm_qk<<<dim3(1024, 2), 256>>>(qkv_ptr);

    // 3) tensor-core flash attention: 36 n-tiles x 16 (b,h) heads
    flash_attn_tc<<<dim3(NTOK / 64, 16), 128, FLASH_SMEM>>>(qkv_ptr, att_ptr);

    // 4) y = w_proj @ att + bias : per batch [256,512] x [512,2304]; 64x128
    //    tiles, 4 warps -> grid 18*4*2 = 144 blocks
    tf32gemm<64, 128, 2, 2><<<dim3(NTOK / 128, CIN / 64, 2), 128>>>(
        w_proj, att_ptr, y, b_proj,
        CIN, NTOK, HID,
        (long long)HID * NTOK, (long long)CIN * NTOK);
}

// round 5
// speedup vs baseline: 3.9824x; 1.4954x over previous
#include <cuda_runtime.h>
#include <cuda_fp16.h>
#include <math.h>
#include <stdint.h>

#define NTOK 2304
#define CIN  256
#define HID  512
#define QKV_M 1536

// Scratch (allocation-free rule: __device__ globals)
__device__ float g_qkv[2u * 1536u * 2304u];   // qkv output: [b][3*512][n]
__device__ float g_att[2u * 512u * 2304u];    // attention output: [b][512][n]
__device__ float g_inv[2048];                 // inv L2 norms: [b][qk][512]

// ---------------------------------------------------------------------------
// helpers
// ---------------------------------------------------------------------------
__device__ __forceinline__ uint32_t packh2(float a, float b) {
    __half2 h = __floats2half2_rn(a, b);
    return *reinterpret_cast<uint32_t*>(&h);
}

__device__ __forceinline__ void mmah(float* c, const uint32_t* a,
                                     uint32_t b0, uint32_t b1) {
    asm volatile(
        "mma.sync.aligned.m16n8k16.row.col.f32.f16.f16.f32 "
        "{%0,%1,%2,%3}, {%4,%5,%6,%7}, {%8,%9}, {%0,%1,%2,%3};\n"
        : "+f"(c[0]), "+f"(c[1]), "+f"(c[2]), "+f"(c[3])
        : "r"(a[0]), "r"(a[1]), "r"(a[2]), "r"(a[3]), "r"(b0), "r"(b1));
}

__device__ __forceinline__ void ldmx2t(uint32_t& r0, uint32_t& r1, const __half* p) {
    uint32_t addr = (uint32_t)__cvta_generic_to_shared(p);
    asm volatile("ldmatrix.sync.aligned.m8n8.x2.trans.shared.b16 {%0,%1}, [%2];"
                 : "=r"(r0), "=r"(r1) : "r"(addr));
}

// ---------------------------------------------------------------------------
// fp16 tensor-core GEMM, double-buffered. C = A(MxK)*B(KxN) (+bias), batched z.
// A row-major [M][K] fp32, B row-major [K][N] fp32, converted to fp16 in smem.
// As stored [m][k] (k contiguous, direct half2 A-frags, stride 40 conflict-free),
// Bs stored [k][n] natural; B-frags via ldmatrix.x2.trans (row stride 4-bank
// spread -> conflict-free). BK=32 (2 k16 mma steps per stage).
// ---------------------------------------------------------------------------
template<int BM, int BN, int WMN, int WNN>
__global__ __launch_bounds__(WMN * WNN * 32) void h16gemm(
    const float* __restrict__ A, const float* __restrict__ Bg,
    float* __restrict__ Cg, const float* __restrict__ bias,
    int M, int N, int K, long long strideB, long long strideC)
{
    constexpr int THREADS = WMN * WNN * 32;
    constexpr int BK  = 32;
    constexpr int AST = BK + 8;      // halves
    constexpr int BST = BN + 8;      // halves
    constexpr int WM = BM / WMN;     // 32
    constexpr int WN = BN / WNN;     // 64 or 32
    constexpr int MT = WM / 16;      // 2
    constexpr int NT = WN / 8;       // 8 or 4
    constexpr int A_F4 = BM * (BK / 4) / THREADS;
    constexpr int B_F4 = BK * (BN / 4) / THREADS;

    __shared__ __half As[2][BM * AST];
    __shared__ __half Bs[2][BK * BST];

    const float* B = Bg + (long long)blockIdx.z * strideB;
    float*       C = Cg + (long long)blockIdx.z * strideC;

    const int m0 = blockIdx.y * BM;
    const int n0 = blockIdx.x * BN;
    const int tid  = threadIdx.x;
    const int w    = tid >> 5;
    const int lane = tid & 31;
    const int g    = lane >> 2;
    const int tg   = lane & 3;
    const int wm   = (w % WMN) * WM;
    const int wn   = (w / WMN) * WN;

    float acc[MT][NT][4];
#pragma unroll
    for (int mt = 0; mt < MT; mt++)
#pragma unroll
        for (int nt = 0; nt < NT; nt++)
#pragma unroll
            for (int j = 0; j < 4; j++) acc[mt][nt][j] = 0.0f;

    int ar[A_F4], ac[A_F4], br[B_F4], bc[B_F4];
#pragma unroll
    for (int i = 0; i < A_F4; i++) {
        int idx = i * THREADS + tid;
        ar[i] = idx >> 3; ac[i] = (idx & 7) << 2;
    }
#pragma unroll
    for (int i = 0; i < B_F4; i++) {
        int idx = i * THREADS + tid;
        br[i] = idx / (BN / 4); bc[i] = (idx % (BN / 4)) << 2;
    }

    float4 av[A_F4], bv[B_F4];

    // prologue: load tile 0, fill stage 0
#pragma unroll
    for (int i = 0; i < A_F4; i++)
        av[i] = *(const float4*)(A + (long long)(m0 + ar[i]) * K + ac[i]);
#pragma unroll
    for (int i = 0; i < B_F4; i++)
        bv[i] = *(const float4*)(B + (long long)br[i] * N + n0 + bc[i]);
#pragma unroll
    for (int i = 0; i < A_F4; i++) {
        *(__half2*)&As[0][ar[i] * AST + ac[i]]     = __floats2half2_rn(av[i].x, av[i].y);
        *(__half2*)&As[0][ar[i] * AST + ac[i] + 2] = __floats2half2_rn(av[i].z, av[i].w);
    }
#pragma unroll
    for (int i = 0; i < B_F4; i++) {
        *(__half2*)&Bs[0][br[i] * BST + bc[i]]     = __floats2half2_rn(bv[i].x, bv[i].y);
        *(__half2*)&Bs[0][br[i] * BST + bc[i] + 2] = __floats2half2_rn(bv[i].z, bv[i].w);
    }
    __syncthreads();

    const int nk = K / BK;
    int cur = 0;
    for (int t = 0; t < nk; t++) {
        const bool more = (t + 1 < nk);
        if (more) {
            const int k0 = (t + 1) * BK;
#pragma unroll
            for (int i = 0; i < A_F4; i++)
                av[i] = *(const float4*)(A + (long long)(m0 + ar[i]) * K + k0 + ac[i]);
#pragma unroll
            for (int i = 0; i < B_F4; i++)
                bv[i] = *(const float4*)(B + (long long)(k0 + br[i]) * N + n0 + bc[i]);
        }

        // compute on stage cur
#pragma unroll
        for (int ks = 0; ks < BK; ks += 16) {
            uint32_t af[MT][4];
#pragma unroll
            for (int mt = 0; mt < MT; mt++) {
                const int r = wm + mt * 16 + g;
                af[mt][0] = *(const uint32_t*)&As[cur][r * AST + ks + 2 * tg];
                af[mt][1] = *(const uint32_t*)&As[cur][(r + 8) * AST + ks + 2 * tg];
                af[mt][2] = *(const uint32_t*)&As[cur][r * AST + ks + 2 * tg + 8];
                af[mt][3] = *(const uint32_t*)&As[cur][(r + 8) * AST + ks + 2 * tg + 8];
            }
#pragma unroll
            for (int nt = 0; nt < NT; nt++) {
                uint32_t b0, b1;
                ldmx2t(b0, b1, &Bs[cur][(ks + (lane & 15)) * BST + wn + nt * 8]);
#pragma unroll
                for (int mt = 0; mt < MT; mt++)
                    mmah(acc[mt][nt], af[mt], b0, b1);
            }
        }

        if (more) {
            const int nxt = cur ^ 1;
#pragma unroll
            for (int i = 0; i < A_F4; i++) {
                *(__half2*)&As[nxt][ar[i] * AST + ac[i]]     = __floats2half2_rn(av[i].x, av[i].y);
                *(__half2*)&As[nxt][ar[i] * AST + ac[i] + 2] = __floats2half2_rn(av[i].z, av[i].w);
            }
#pragma unroll
            for (int i = 0; i < B_F4; i++) {
                *(__half2*)&Bs[nxt][br[i] * BST + bc[i]]     = __floats2half2_rn(bv[i].x, bv[i].y);
                *(__half2*)&Bs[nxt][br[i] * BST + bc[i] + 2] = __floats2half2_rn(bv[i].z, bv[i].w);
            }
            __syncthreads();
            cur = nxt;
        }
    }

    // Epilogue
#pragma unroll
    for (int mt = 0; mt < MT; mt++) {
        const int r0 = m0 + wm + mt * 16 + g;
        const float bs0 = bias ? bias[r0]     : 0.0f;
        const float bs1 = bias ? bias[r0 + 8] : 0.0f;
#pragma unroll
        for (int nt = 0; nt < NT; nt++) {
            const int cidx = n0 + wn + nt * 8 + 2 * tg;
            *(float2*)(C + (long long)r0 * N + cidx) =
                make_float2(acc[mt][nt][0] + bs0, acc[mt][nt][1] + bs0);
            *(float2*)(C + (long long)(r0 + 8) * N + cidx) =
                make_float2(acc[mt][nt][2] + bs1, acc[mt][nt][3] + bs1);
        }
    }
}

// ---------------------------------------------------------------------------
// L2 inverse norms of q and k rows (no write-back of scaled rows).
// grid (1024, B): r -> {qk, row}; writes inv[b*1024 + r].
// ---------------------------------------------------------------------------
__global__ __launch_bounds__(256) void l2inv(const float* __restrict__ qkv,
                                             float* __restrict__ inv)
{
    const int b = blockIdx.y;
    const int r = blockIdx.x;
    const float* row = qkv + ((long long)b * 3 * HID + (r >> 9) * HID + (r & 511)) * NTOK;
    const int tid = threadIdx.x;

    float s = 0.0f;
    for (int i = tid; i < NTOK; i += 256) { float v = row[i]; s += v * v; }
#pragma unroll
    for (int o = 16; o >= 1; o >>= 1) s += __shfl_xor_sync(0xffffffffu, s, o);

    __shared__ float ws[8];
    if ((tid & 31) == 0) ws[tid >> 5] = s;
    __syncthreads();
    if (tid == 0) {
        float t = 0.0f;
#pragma unroll
        for (int i = 0; i < 8; i++) t += ws[i];
        inv[b * 1024 + r] = 1.0f / fmaxf(sqrtf(t), 1e-12f);
    }
}

// ---------------------------------------------------------------------------
// fp16 tensor-core flash attention.
// Block = 128 threads (4 warps), one (b,h) head (blockIdx.y), 64-token n-tile
// (blockIdx.x). Q/K scaled by inv norms on load. sK/sV stored [d][m] natural
// (STS.64 conflict-free); phase A K-fragments via ldmatrix.x2.trans; sP stored
// [n][m]; all strides 72 halves -> conflict-free fragment accesses.
// ---------------------------------------------------------------------------
#define SKT 72

__global__ __launch_bounds__(128) void flash_attn_h(
    const float* __restrict__ qkv, const float* __restrict__ inv,
    float* __restrict__ outp)
{
    __shared__ __half sK[64 * SKT];
    __shared__ __half sV[64 * SKT];
    __shared__ __half sP[64 * SKT];
    __shared__ float  sC[64];

    const int b  = blockIdx.y >> 3;
    const int h  = blockIdx.y & 7;
    const int n0 = blockIdx.x * 64;

    const float* Q  = qkv + ((long long)(b * 3 * HID + h * 64)) * NTOK;
    const float* Kp = Q + (long long)HID * NTOK;
    const float* Vp = Q + 2LL * HID * NTOK;
    const float* invQ = inv + b * 1024 + h * 64;
    const float* invK = invQ + 512;

    const int tid  = threadIdx.x;
    const int w    = tid >> 5;
    const int lane = tid & 31;
    const int g    = lane >> 2;
    const int tg   = lane & 3;

    // Q^T A-fragments (rows n, cols d), scaled by invQ[d], held all 36 tiles.
    uint32_t qa[4][4];
    {
        const int nA = n0 + w * 16 + g;
#pragma unroll
        for (int kk = 0; kk < 4; kk++) {
            const int d0 = kk * 16 + 2 * tg;
            const float i0 = invQ[d0],     i1 = invQ[d0 + 1];
            const float i8 = invQ[d0 + 8], i9 = invQ[d0 + 9];
            qa[kk][0] = packh2(Q[(long long)d0 * NTOK + nA] * i0,
                               Q[(long long)(d0 + 1) * NTOK + nA] * i1);
            qa[kk][1] = packh2(Q[(long long)d0 * NTOK + nA + 8] * i0,
                               Q[(long long)(d0 + 1) * NTOK + nA + 8] * i1);
            qa[kk][2] = packh2(Q[(long long)(d0 + 8) * NTOK + nA] * i8,
                               Q[(long long)(d0 + 9) * NTOK + nA] * i9);
            qa[kk][3] = packh2(Q[(long long)(d0 + 8) * NTOK + nA + 8] * i8,
                               Q[(long long)(d0 + 9) * NTOK + nA + 8] * i9);
        }
    }

    float oc[8][4];
#pragma unroll
    for (int t = 0; t < 8; t++)
#pragma unroll
        for (int j = 0; j < 4; j++) oc[t][j] = 0.0f;

    float rmax[2] = {-1e30f, -1e30f};
    float rsum[2] = {0.0f, 0.0f};

    for (int m0 = 0; m0 < NTOK; m0 += 64) {
        __syncthreads();

        // Load K (scaled) and V tiles as fp16, natural [d][m] layout.
#pragma unroll
        for (int p = 0; p < 8; p++) {
            const int idx = p * 512 + tid * 4;
            const int d = idx >> 6, m = idx & 63;
            float4 kv = *(const float4*)(Kp + (long long)d * NTOK + m0 + m);
            float4 vv = *(const float4*)(Vp + (long long)d * NTOK + m0 + m);
            const float ik = invK[d];
            *(__half2*)&sK[d * SKT + m]     = __floats2half2_rn(kv.x * ik, kv.y * ik);
            *(__half2*)&sK[d * SKT + m + 2] = __floats2half2_rn(kv.z * ik, kv.w * ik);
            *(__half2*)&sV[d * SKT + m]     = __floats2half2_rn(vv.x, vv.y);
            *(__half2*)&sV[d * SKT + m + 2] = __floats2half2_rn(vv.z, vv.w);
        }
        __syncthreads();

        // ---- Phase A: S = Q^T K ----
        float sc[8][4];
#pragma unroll
        for (int t = 0; t < 8; t++)
#pragma unroll
            for (int j = 0; j < 4; j++) sc[t][j] = 0.0f;

#pragma unroll
        for (int kk = 0; kk < 4; kk++) {
            const __half* krow = &sK[(kk * 16 + (lane & 15)) * SKT];
#pragma unroll
            for (int t = 0; t < 8; t++) {
                uint32_t b0, b1;
                ldmx2t(b0, b1, krow + t * 8);
                mmah(sc[t], qa[kk], b0, b1);
            }
        }

        // ---- Online softmax ----
        const int nloc = w * 16 + g;
#pragma unroll
        for (int r = 0; r < 2; r++) {
            float mx = -1e30f;
#pragma unroll
            for (int t = 0; t < 8; t++)
                mx = fmaxf(mx, fmaxf(sc[t][2 * r], sc[t][2 * r + 1]));
            mx = fmaxf(mx, __shfl_xor_sync(0xffffffffu, mx, 1));
            mx = fmaxf(mx, __shfl_xor_sync(0xffffffffu, mx, 2));
            const float nm   = fmaxf(rmax[r], mx);
            const float corr = __expf(rmax[r] - nm);
            rmax[r] = nm;
            float ps = 0.0f;
            __half* prow = sP + (nloc + 8 * r) * SKT + 2 * tg;
#pragma unroll
            for (int t = 0; t < 8; t++) {
                float e0 = __expf(sc[t][2 * r] - nm);
                float e1 = __expf(sc[t][2 * r + 1] - nm);
                ps += e0 + e1;
                *(__half2*)(prow + t * 8) = __floats2half2_rn(e0, e1);
            }
            ps += __shfl_xor_sync(0xffffffffu, ps, 1);
            ps += __shfl_xor_sync(0xffffffffu, ps, 2);
            rsum[r] = rsum[r] * corr + ps;
            if (tg == 0) sC[nloc + 8 * r] = corr;
        }
        __syncthreads();

        // ---- Phase B: O^T += V * P^T ----
#pragma unroll
        for (int t = 0; t < 8; t++) {
            float c0 = sC[t * 8 + 2 * tg];
            float c1 = sC[t * 8 + 2 * tg + 1];
            oc[t][0] *= c0; oc[t][1] *= c1;
            oc[t][2] *= c0; oc[t][3] *= c1;
        }
        const int vr = w * 16 + g;
#pragma unroll
        for (int kk = 0; kk < 4; kk++) {
            const int mk = kk * 16 + 2 * tg;
            uint32_t a[4];
            a[0] = *(const uint32_t*)&sV[vr * SKT + mk];
            a[1] = *(const uint32_t*)&sV[(vr + 8) * SKT + mk];
            a[2] = *(const uint32_t*)&sV[vr * SKT + mk + 8];
            a[3] = *(const uint32_t*)&sV[(vr + 8) * SKT + mk + 8];
#pragma unroll
            for (int t = 0; t < 8; t++) {
                uint32_t b0 = *(const uint32_t*)&sP[(t * 8 + g) * SKT + mk];
                uint32_t b1 = *(const uint32_t*)&sP[(t * 8 + g) * SKT + mk + 8];
                mmah(oc[t], a, b0, b1);
            }
        }
    }

    // ---- Epilogue ----
    __syncthreads();
    if (tg == 0) {
        sC[w * 16 + g]     = rsum[0];
        sC[w * 16 + g + 8] = rsum[1];
    }
    __syncthreads();

    float* Op = outp + ((long long)(b * HID + h * 64 + w * 16)) * NTOK + n0;
#pragma unroll
    for (int t = 0; t < 8; t++) {
        const int n = t * 8 + 2 * tg;
        const float i0 = 1.0f / sC[n];
        const float i1 = 1.0f / sC[n + 1];
        Op[(long long)g * NTOK + n]           = oc[t][0] * i0;
        Op[(long long)g * NTOK + n + 1]       = oc[t][1] * i1;
        Op[(long long)(g + 8) * NTOK + n]     = oc[t][2] * i0;
        Op[(long long)(g + 8) * NTOK + n + 1] = oc[t][3] * i1;
    }
}

// ---------------------------------------------------------------------------
extern "C" void kernel_launch(void* const* d_in, const int* in_sizes, int n_in,
                              void* d_out, int out_size)
{
    const float* x      = (const float*)d_in[0];   // (2, 256, 48, 48)
    const float* w_qkv  = (const float*)d_in[1];   // (1536, 256)
    const float* w_proj = (const float*)d_in[2];   // (256, 512)
    const float* b_proj = (const float*)d_in[3];   // (256,)
    float* y = (float*)d_out;                      // (2, 256, 48, 48)

    float *qkv_ptr = nullptr, *att_ptr = nullptr, *inv_ptr = nullptr;
    cudaGetSymbolAddress((void**)&qkv_ptr, g_qkv);
    cudaGetSymbolAddress((void**)&att_ptr, g_att);
    cudaGetSymbolAddress((void**)&inv_ptr, g_inv);

    // 1) qkv = w_qkv @ x : per batch [1536,256] x [256,2304]
    h16gemm<128, 128, 4, 2><<<dim3(NTOK / 128, QKV_M / 128, 2), 256>>>(
        w_qkv, x, qkv_ptr, nullptr,
        QKV_M, NTOK, CIN,
        (long long)CIN * NTOK, (long long)QKV_M * NTOK);

    // 2) inverse L2 norms of q/k rows (no write-back)
    l2inv<<<dim3(1024, 2), 256>>>(qkv_ptr, inv_ptr);

    // 3) fp16 tensor-core flash attention: 36 n-tiles x 16 (b,h) heads
    flash_attn_h<<<dim3(NTOK / 64, 16), 128>>>(qkv_ptr, inv_ptr, att_ptr);

    // 4) y = w_proj @ att + bias : per batch [256,512] x [512,2304]
    h16gemm<64, 64, 2, 2><<<dim3(NTOK / 64, CIN / 64, 2), 128>>>(
        w_proj, att_ptr, y, b_proj,
        CIN, NTOK, HID,
        (long long)HID * NTOK, (long long)CIN * NTOK);
}

// round 6
// speedup vs baseline: 5.3415x; 1.3413x over previous
#include <cuda_runtime.h>
#include <cuda_fp16.h>
#include <math.h>
#include <stdint.h>

#define NTOK 2304
#define CIN  256
#define HID  512
#define QKV_M 1536

// Scratch (allocation-free rule: __device__ globals) — fp16 intermediates
__device__ __half g_qkv[2u * 1536u * 2304u];  // qkv: [b][3*512][n]
__device__ __half g_att[2u * 512u * 2304u];   // attention out: [b][512][n]
__device__ float  g_inv[2048];                // inv L2 norms: [b][qk][512]

// ---------------------------------------------------------------------------
// helpers
// ---------------------------------------------------------------------------
__device__ __forceinline__ uint32_t packh2(float a, float b) {
    __half2 h = __floats2half2_rn(a, b);
    return *reinterpret_cast<uint32_t*>(&h);
}

__device__ __forceinline__ void mmah(float* c, const uint32_t* a,
                                     uint32_t b0, uint32_t b1) {
    asm volatile(
        "mma.sync.aligned.m16n8k16.row.col.f32.f16.f16.f32 "
        "{%0,%1,%2,%3}, {%4,%5,%6,%7}, {%8,%9}, {%0,%1,%2,%3};\n"
        : "+f"(c[0]), "+f"(c[1]), "+f"(c[2]), "+f"(c[3])
        : "r"(a[0]), "r"(a[1]), "r"(a[2]), "r"(a[3]), "r"(b0), "r"(b1));
}

__device__ __forceinline__ void ldmx2t(uint32_t& r0, uint32_t& r1, const __half* p) {
    uint32_t addr = (uint32_t)__cvta_generic_to_shared(p);
    asm volatile("ldmatrix.sync.aligned.m8n8.x2.trans.shared.b16 {%0,%1}, [%2];"
                 : "=r"(r0), "=r"(r1) : "r"(addr));
}

// ---------------------------------------------------------------------------
// fp16 tensor-core GEMM, double-buffered. C = A(MxK)*B(KxN) (+bias), batched z.
// A fp32 row-major; B fp32 or fp16 row-major (TB); C fp32 or fp16 (TC).
// As stored [m][k] (direct half2 A-frags); Bs [k][n]; B-frags via ldmatrix.trans.
// ---------------------------------------------------------------------------
template<int BM, int BN, int WMN, int WNN, typename TB, typename TC>
__global__ __launch_bounds__(WMN * WNN * 32) void h16gemm(
    const float* __restrict__ A, const TB* __restrict__ Bg,
    TC* __restrict__ Cg, const float* __restrict__ bias,
    int M, int N, int K, long long strideB, long long strideC)
{
    constexpr int THREADS = WMN * WNN * 32;
    constexpr int BK  = 32;
    constexpr int AST = BK + 8;
    constexpr int BST = BN + 8;
    constexpr int WM = BM / WMN;
    constexpr int WN = BN / WNN;
    constexpr int MT = WM / 16;
    constexpr int NT = WN / 8;
    constexpr int A_F4 = BM * (BK / 4) / THREADS;
    constexpr int B_F4 = BK * (BN / 4) / THREADS;
    constexpr bool BH = (sizeof(TB) == 2);
    constexpr bool CH = (sizeof(TC) == 2);

    __shared__ __half As[2][BM * AST];
    __shared__ __half Bs[2][BK * BST];

    const TB* B = Bg + (long long)blockIdx.z * strideB;
    TC*       C = Cg + (long long)blockIdx.z * strideC;

    const int m0 = blockIdx.y * BM;
    const int n0 = blockIdx.x * BN;
    const int tid  = threadIdx.x;
    const int w    = tid >> 5;
    const int lane = tid & 31;
    const int g    = lane >> 2;
    const int tg   = lane & 3;
    const int wm   = (w % WMN) * WM;
    const int wn   = (w / WMN) * WN;

    float acc[MT][NT][4];
#pragma unroll
    for (int mt = 0; mt < MT; mt++)
#pragma unroll
        for (int nt = 0; nt < NT; nt++)
#pragma unroll
            for (int j = 0; j < 4; j++) acc[mt][nt][j] = 0.0f;

    int ar[A_F4], ac[A_F4], br[B_F4], bc[B_F4];
#pragma unroll
    for (int i = 0; i < A_F4; i++) {
        int idx = i * THREADS + tid;
        ar[i] = idx >> 3; ac[i] = (idx & 7) << 2;
    }
#pragma unroll
    for (int i = 0; i < B_F4; i++) {
        int idx = i * THREADS + tid;
        br[i] = idx / (BN / 4); bc[i] = (idx % (BN / 4)) << 2;
    }

    float4 av[A_F4];
    float4 bvf[B_F4];
    uint2  bvh[B_F4];

    auto loadA = [&](int k0) {
#pragma unroll
        for (int i = 0; i < A_F4; i++)
            av[i] = *(const float4*)(A + (long long)(m0 + ar[i]) * K + k0 + ac[i]);
    };
    auto loadB = [&](int k0) {
#pragma unroll
        for (int i = 0; i < B_F4; i++) {
            if constexpr (BH)
                bvh[i] = *(const uint2*)(B + (long long)(k0 + br[i]) * N + n0 + bc[i]);
            else
                bvf[i] = *(const float4*)(B + (long long)(k0 + br[i]) * N + n0 + bc[i]);
        }
    };
    auto stageA = [&](int s) {
#pragma unroll
        for (int i = 0; i < A_F4; i++) {
            *(__half2*)&As[s][ar[i] * AST + ac[i]]     = __floats2half2_rn(av[i].x, av[i].y);
            *(__half2*)&As[s][ar[i] * AST + ac[i] + 2] = __floats2half2_rn(av[i].z, av[i].w);
        }
    };
    auto stageB = [&](int s) {
#pragma unroll
        for (int i = 0; i < B_F4; i++) {
            if constexpr (BH) {
                *(uint32_t*)&Bs[s][br[i] * BST + bc[i]]     = bvh[i].x;
                *(uint32_t*)&Bs[s][br[i] * BST + bc[i] + 2] = bvh[i].y;
            } else {
                *(__half2*)&Bs[s][br[i] * BST + bc[i]]     = __floats2half2_rn(bvf[i].x, bvf[i].y);
                *(__half2*)&Bs[s][br[i] * BST + bc[i] + 2] = __floats2half2_rn(bvf[i].z, bvf[i].w);
            }
        }
    };

    loadA(0); loadB(0);
    stageA(0); stageB(0);
    __syncthreads();

    const int nk = K / BK;
    int cur = 0;
    for (int t = 0; t < nk; t++) {
        const bool more = (t + 1 < nk);
        if (more) { loadA((t + 1) * BK); loadB((t + 1) * BK); }

#pragma unroll
        for (int ks = 0; ks < BK; ks += 16) {
            uint32_t af[MT][4];
#pragma unroll
            for (int mt = 0; mt < MT; mt++) {
                const int r = wm + mt * 16 + g;
                af[mt][0] = *(const uint32_t*)&As[cur][r * AST + ks + 2 * tg];
                af[mt][1] = *(const uint32_t*)&As[cur][(r + 8) * AST + ks + 2 * tg];
                af[mt][2] = *(const uint32_t*)&As[cur][r * AST + ks + 2 * tg + 8];
                af[mt][3] = *(const uint32_t*)&As[cur][(r + 8) * AST + ks + 2 * tg + 8];
            }
#pragma unroll
            for (int nt = 0; nt < NT; nt++) {
                uint32_t b0, b1;
                ldmx2t(b0, b1, &Bs[cur][(ks + (lane & 15)) * BST + wn + nt * 8]);
#pragma unroll
                for (int mt = 0; mt < MT; mt++)
                    mmah(acc[mt][nt], af[mt], b0, b1);
            }
        }

        if (more) {
            const int nxt = cur ^ 1;
            stageA(nxt); stageB(nxt);
            __syncthreads();
            cur = nxt;
        }
    }

    // Epilogue
#pragma unroll
    for (int mt = 0; mt < MT; mt++) {
        const int r0 = m0 + wm + mt * 16 + g;
        const float bs0 = bias ? bias[r0]     : 0.0f;
        const float bs1 = bias ? bias[r0 + 8] : 0.0f;
#pragma unroll
        for (int nt = 0; nt < NT; nt++) {
            const int cidx = n0 + wn + nt * 8 + 2 * tg;
            if constexpr (CH) {
                *(__half2*)(C + (long long)r0 * N + cidx) =
                    __floats2half2_rn(acc[mt][nt][0] + bs0, acc[mt][nt][1] + bs0);
                *(__half2*)(C + (long long)(r0 + 8) * N + cidx) =
                    __floats2half2_rn(acc[mt][nt][2] + bs1, acc[mt][nt][3] + bs1);
            } else {
                *(float2*)(C + (long long)r0 * N + cidx) =
                    make_float2(acc[mt][nt][0] + bs0, acc[mt][nt][1] + bs0);
                *(float2*)(C + (long long)(r0 + 8) * N + cidx) =
                    make_float2(acc[mt][nt][2] + bs1, acc[mt][nt][3] + bs1);
            }
        }
    }
}

// ---------------------------------------------------------------------------
// L2 inverse norms of q/k rows (fp16 input, fp32 accumulate).
// ---------------------------------------------------------------------------
__global__ __launch_bounds__(256) void l2inv(const __half* __restrict__ qkv,
                                             float* __restrict__ inv)
{
    const int b = blockIdx.y;
    const int r = blockIdx.x;
    const __half2* row = (const __half2*)(qkv +
        ((long long)b * 3 * HID + (r >> 9) * HID + (r & 511)) * NTOK);
    const int tid = threadIdx.x;

    float s = 0.0f;
    for (int i = tid; i < NTOK / 2; i += 256) {
        float2 v = __half22float2(row[i]);
        s += v.x * v.x + v.y * v.y;
    }
#pragma unroll
    for (int o = 16; o >= 1; o >>= 1) s += __shfl_xor_sync(0xffffffffu, s, o);

    __shared__ float ws[8];
    if ((tid & 31) == 0) ws[tid >> 5] = s;
    __syncthreads();
    if (tid == 0) {
        float t = 0.0f;
#pragma unroll
        for (int i = 0; i < 8; i++) t += ws[i];
        inv[b * 1024 + r] = 1.0f / fmaxf(sqrtf(t), 1e-12f);
    }
}

// ---------------------------------------------------------------------------
// fp16 tensor-core flash attention, 128-token q-tile per block (8 warps).
// Both invQ and invK folded into the register-resident Q fragments, so K/V
// loads are raw half2 copies. Phase A: warp w -> S rows [w*16,+16) x 64 m.
// Phase B: warp -> d strip (w&3)*16 x n half (w>>2)*64 of O^T += V*P^T.
// ---------------------------------------------------------------------------
#define SKT 72

__global__ __launch_bounds__(256) void flash_attn_h(
    const __half* __restrict__ qkv, const float* __restrict__ inv,
    __half* __restrict__ outp)
{
    __shared__ __half sK[64 * SKT];
    __shared__ __half sV[64 * SKT];
    __shared__ __half sP[128 * SKT];
    __shared__ float  sC[128];

    const int b  = blockIdx.y >> 3;
    const int h  = blockIdx.y & 7;
    const int n0 = blockIdx.x * 128;

    const __half* Q  = qkv + ((long long)(b * 3 * HID + h * 64)) * NTOK;
    const __half* Kp = Q + (long long)HID * NTOK;
    const __half* Vp = Q + 2LL * HID * NTOK;
    const float* invQ = inv + b * 1024 + h * 64;
    const float* invK = invQ + 512;

    const int tid  = threadIdx.x;
    const int w    = tid >> 5;
    const int lane = tid & 31;
    const int g    = lane >> 2;
    const int tg   = lane & 3;
    const int dstrip = (w & 3) * 16;   // phase B d strip
    const int nhalf  = (w >> 2) * 64;  // phase B n half

    // Q^T A-fragments scaled by invQ[d]*invK[d]; reused for all 36 KV tiles.
    uint32_t qa[4][4];
    {
        const int nA = n0 + w * 16 + g;
#pragma unroll
        for (int kk = 0; kk < 4; kk++) {
            const int d0 = kk * 16 + 2 * tg;
            const float s0 = invQ[d0]     * invK[d0];
            const float s1 = invQ[d0 + 1] * invK[d0 + 1];
            const float s8 = invQ[d0 + 8] * invK[d0 + 8];
            const float s9 = invQ[d0 + 9] * invK[d0 + 9];
            qa[kk][0] = packh2(__half2float(Q[(long long)d0 * NTOK + nA]) * s0,
                               __half2float(Q[(long long)(d0 + 1) * NTOK + nA]) * s1);
            qa[kk][1] = packh2(__half2float(Q[(long long)d0 * NTOK + nA + 8]) * s0,
                               __half2float(Q[(long long)(d0 + 1) * NTOK + nA + 8]) * s1);
            qa[kk][2] = packh2(__half2float(Q[(long long)(d0 + 8) * NTOK + nA]) * s8,
                               __half2float(Q[(long long)(d0 + 9) * NTOK + nA]) * s9);
            qa[kk][3] = packh2(__half2float(Q[(long long)(d0 + 8) * NTOK + nA + 8]) * s8,
                               __half2float(Q[(long long)(d0 + 9) * NTOK + nA + 8]) * s9);
        }
    }

    float oc[8][4];
#pragma unroll
    for (int t = 0; t < 8; t++)
#pragma unroll
        for (int j = 0; j < 4; j++) oc[t][j] = 0.0f;

    float rmax[2] = {-1e30f, -1e30f};
    float rsum[2] = {0.0f, 0.0f};

    for (int m0 = 0; m0 < NTOK; m0 += 64) {
        __syncthreads();

        // Load K/V tiles: raw half copies, natural [d][m] layout.
#pragma unroll
        for (int p = 0; p < 4; p++) {
            const int idx = (p * 256 + tid) * 4;    // element offset, 0..4095
            const int d = idx >> 6, m = idx & 63;
            *(uint2*)&sK[d * SKT + m] = *(const uint2*)(Kp + (long long)d * NTOK + m0 + m);
            *(uint2*)&sV[d * SKT + m] = *(const uint2*)(Vp + (long long)d * NTOK + m0 + m);
        }
        __syncthreads();

        // ---- Phase A: S = Q^T K ----
        float sc[8][4];
#pragma unroll
        for (int t = 0; t < 8; t++)
#pragma unroll
            for (int j = 0; j < 4; j++) sc[t][j] = 0.0f;

#pragma unroll
        for (int kk = 0; kk < 4; kk++) {
            const __half* krow = &sK[(kk * 16 + (lane & 15)) * SKT];
#pragma unroll
            for (int t = 0; t < 8; t++) {
                uint32_t b0, b1;
                ldmx2t(b0, b1, krow + t * 8);
                mmah(sc[t], qa[kk], b0, b1);
            }
        }

        // ---- Online softmax (warp w owns rows w*16..w*16+15) ----
        const int nloc = w * 16 + g;
#pragma unroll
        for (int r = 0; r < 2; r++) {
            float mx = -1e30f;
#pragma unroll
            for (int t = 0; t < 8; t++)
                mx = fmaxf(mx, fmaxf(sc[t][2 * r], sc[t][2 * r + 1]));
            mx = fmaxf(mx, __shfl_xor_sync(0xffffffffu, mx, 1));
            mx = fmaxf(mx, __shfl_xor_sync(0xffffffffu, mx, 2));
            const float nm   = fmaxf(rmax[r], mx);
            const float corr = __expf(rmax[r] - nm);
            rmax[r] = nm;
            float ps = 0.0f;
            __half* prow = sP + (nloc + 8 * r) * SKT + 2 * tg;
#pragma unroll
            for (int t = 0; t < 8; t++) {
                float e0 = __expf(sc[t][2 * r] - nm);
                float e1 = __expf(sc[t][2 * r + 1] - nm);
                ps += e0 + e1;
                *(__half2*)(prow + t * 8) = __floats2half2_rn(e0, e1);
            }
            ps += __shfl_xor_sync(0xffffffffu, ps, 1);
            ps += __shfl_xor_sync(0xffffffffu, ps, 2);
            rsum[r] = rsum[r] * corr + ps;
            if (tg == 0) sC[nloc + 8 * r] = corr;
        }
        __syncthreads();

        // ---- Phase B: O^T += V * P^T (warp: d strip x n half) ----
#pragma unroll
        for (int t = 0; t < 8; t++) {
            float c0 = sC[nhalf + t * 8 + 2 * tg];
            float c1 = sC[nhalf + t * 8 + 2 * tg + 1];
            oc[t][0] *= c0; oc[t][1] *= c1;
            oc[t][2] *= c0; oc[t][3] *= c1;
        }
        const int vr = dstrip + g;
#pragma unroll
        for (int kk = 0; kk < 4; kk++) {
            const int mk = kk * 16 + 2 * tg;
            uint32_t a[4];
            a[0] = *(const uint32_t*)&sV[vr * SKT + mk];
            a[1] = *(const uint32_t*)&sV[(vr + 8) * SKT + mk];
            a[2] = *(const uint32_t*)&sV[vr * SKT + mk + 8];
            a[3] = *(const uint32_t*)&sV[(vr + 8) * SKT + mk + 8];
#pragma unroll
            for (int t = 0; t < 8; t++) {
                uint32_t b0 = *(const uint32_t*)&sP[(nhalf + t * 8 + g) * SKT + mk];
                uint32_t b1 = *(const uint32_t*)&sP[(nhalf + t * 8 + g) * SKT + mk + 8];
                mmah(oc[t], a, b0, b1);
            }
        }
    }

    // ---- Epilogue ----
    __syncthreads();
    if (tg == 0) {
        sC[w * 16 + g]     = rsum[0];
        sC[w * 16 + g + 8] = rsum[1];
    }
    __syncthreads();

    __half* Op = outp + ((long long)(b * HID + h * 64 + dstrip)) * NTOK + n0 + nhalf;
#pragma unroll
    for (int t = 0; t < 8; t++) {
        const int n = t * 8 + 2 * tg;
        const float i0 = 1.0f / sC[nhalf + n];
        const float i1 = 1.0f / sC[nhalf + n + 1];
        *(__half2*)(Op + (long long)g * NTOK + n) =
            __floats2half2_rn(oc[t][0] * i0, oc[t][1] * i1);
        *(__half2*)(Op + (long long)(g + 8) * NTOK + n) =
            __floats2half2_rn(oc[t][2] * i0, oc[t][3] * i1);
    }
}

// ---------------------------------------------------------------------------
extern "C" void kernel_launch(void* const* d_in, const int* in_sizes, int n_in,
                              void* d_out, int out_size)
{
    const float* x      = (const float*)d_in[0];   // (2, 256, 48, 48)
    const float* w_qkv  = (const float*)d_in[1];   // (1536, 256)
    const float* w_proj = (const float*)d_in[2];   // (256, 512)
    const float* b_proj = (const float*)d_in[3];   // (256,)
    float* y = (float*)d_out;                      // (2, 256, 48, 48)

    __half *qkv_ptr = nullptr, *att_ptr = nullptr;
    float  *inv_ptr = nullptr;
    cudaGetSymbolAddress((void**)&qkv_ptr, g_qkv);
    cudaGetSymbolAddress((void**)&att_ptr, g_att);
    cudaGetSymbolAddress((void**)&inv_ptr, g_inv);

    // 1) qkv = w_qkv @ x : [1536,256] x [256,2304] per batch, fp16 out
    h16gemm<128, 128, 4, 2, float, __half>
        <<<dim3(NTOK / 128, QKV_M / 128, 2), 256>>>(
        w_qkv, x, qkv_ptr, nullptr,
        QKV_M, NTOK, CIN,
        (long long)CIN * NTOK, (long long)QKV_M * NTOK);

    // 2) inverse L2 norms of q/k rows
    l2inv<<<dim3(1024, 2), 256>>>(qkv_ptr, inv_ptr);

    // 3) flash attention: 18 q-tiles x 16 (b,h) heads, fp16 in/out
    flash_attn_h<<<dim3(NTOK / 128, 16), 256>>>(qkv_ptr, inv_ptr, att_ptr);

    // 4) y = w_proj @ att + bias : [256,512] x [512,2304] per batch, fp32 out
    h16gemm<64, 64, 2, 2, __half, float>
        <<<dim3(NTOK / 64, CIN / 64, 2), 128>>>(
        w_proj, att_ptr, y, b_proj,
        CIN, NTOK, HID,
        (long long)HID * NTOK, (long long)CIN * NTOK);
}